// round 4
// baseline (speedup 1.0000x reference)
#include <cuda_runtime.h>
#include <math.h>
#include <stdint.h>

#define BSZ 1024
#define DD  1024
#define LDCP 11008   // padded leading dim for logits (11003 -> 11008)

// ---------------- scratch (device globals; no allocations allowed) ----------
__device__ float g_norm[2 * BSZ * DD];          // rows 0..1023 = vn, 1024..2047 = tn
__device__ float g_normhl[2 * BSZ * 2 * DD];    // interleaved (hi,lo) per element
__device__ float g_projhl[2 * BSZ * 2 * DD];    // interleaved (hi,lo) of vpt / tpv
__device__ float g_vhl[BSZ * 2 * DD];
__device__ float g_thl[BSZ * 2 * DD];
__device__ float g_Whl[DD * 2 * LDCP];          // pad cols zero (never written)
__device__ float g_W2hl[DD * 2 * LDCP];
__device__ float g_invW[LDCP];
__device__ float g_invW2[LDCP];
__device__ float g_logits1[2 * BSZ * LDCP];     // pad cols stay 0 (zero-init, never written)
__device__ float g_logits2[2 * BSZ * LDCP];
__device__ float g_sim[BSZ * BSZ];
__device__ float g_vp[BSZ * BSZ];
__device__ float g_tp[BSZ * BSZ];
__device__ float g_diag[BSZ];
__device__ int   g_cnt[256];
__device__ int   g_colmax[BSZ];                 // float bits, values >= 0
__device__ double g_acc[6];                     // 0:ce1 1:ce2 2:ga 3:cmpm_v 4:cmpm_t 5:rowmax_sum
__device__ int   g_prec[2];

// ---------------- helpers ----------------------------------------------------
__device__ __forceinline__ float softplus_ref(float x) {
    return (x > 20.f) ? x : log1pf(__expf(x));
}

// split x into tf32 hi + tf32 lo (both stored as fp32 bit patterns)
__device__ __forceinline__ float2 split2(float x) {
    uint32_t h;
    asm("cvt.rna.tf32.f32 %0, %1;" : "=r"(h) : "f"(x));
    float hf = __uint_as_float(h);
    float l = x - hf;
    uint32_t lw;
    asm("cvt.rna.tf32.f32 %0, %1;" : "=r"(lw) : "f"(l));
    return make_float2(hf, __uint_as_float(lw));
}

__device__ __forceinline__ void mma_tf32(float* c, const uint32_t* a, const uint32_t* b) {
    asm volatile(
        "mma.sync.aligned.m16n8k8.row.col.f32.tf32.tf32.f32 "
        "{%0,%1,%2,%3}, {%4,%5,%6,%7}, {%8,%9}, {%0,%1,%2,%3};"
        : "+f"(c[0]), "+f"(c[1]), "+f"(c[2]), "+f"(c[3])
        : "r"(a[0]), "r"(a[1]), "r"(a[2]), "r"(a[3]), "r"(b[0]), "r"(b[1]));
}

// ---------------- init / histogram ------------------------------------------
__global__ void init_kernel() {
    int t = blockIdx.x * blockDim.x + threadIdx.x;
    if (t < 6)    g_acc[t] = 0.0;
    if (t < 2)    g_prec[t] = 0;
    if (t < 256)  g_cnt[t] = 0;
    if (t < BSZ)  g_colmax[t] = 0;
}

__global__ void hist_kernel(const int* __restrict__ labels) {
    int t = blockIdx.x * blockDim.x + threadIdx.x;
    if (t < BSZ) atomicAdd(&g_cnt[labels[t]], 1);
}

// ---------------- row normalize (vn, tn) + tf32 split -------------------------
__global__ void __launch_bounds__(256) normalize_kernel(const float* __restrict__ v,
                                                        const float* __restrict__ t) {
    __shared__ float red[256];
    int r = blockIdx.x;                     // 0..2047
    const float* src = (r < BSZ ? v : t) + (size_t)(r & (BSZ - 1)) * DD;
    float s = 0.f;
    for (int d = threadIdx.x; d < DD; d += 256) { float x = src[d]; s += x * x; }
    red[threadIdx.x] = s; __syncthreads();
    for (int st = 128; st > 0; st >>= 1) {
        if (threadIdx.x < st) red[threadIdx.x] += red[threadIdx.x + st];
        __syncthreads();
    }
    float inv = 1.f / sqrtf(red[0]);
    float* dst = g_norm + (size_t)r * DD;
    float2* dhl = (float2*)g_normhl + (size_t)r * DD;
    for (int d = threadIdx.x; d < DD; d += 256) {
        float x = src[d] * inv;
        dst[d] = x;
        dhl[d] = split2(x);
    }
}

// ---------------- projections vpt, tpv (split output) -------------------------
__global__ void __launch_bounds__(256) proj_kernel(const float* __restrict__ v,
                                                   const float* __restrict__ t) {
    __shared__ float r1[256], r2[256];
    int i = blockIdx.x;
    const float* vn = g_norm + (size_t)i * DD;
    const float* tn = g_norm + (size_t)(BSZ + i) * DD;
    const float* vi = v + (size_t)i * DD;
    const float* ti = t + (size_t)i * DD;
    float a = 0.f, b = 0.f;
    for (int d = threadIdx.x; d < DD; d += 256) { a += vi[d] * tn[d]; b += ti[d] * vn[d]; }
    r1[threadIdx.x] = a; r2[threadIdx.x] = b; __syncthreads();
    for (int st = 128; st > 0; st >>= 1) {
        if (threadIdx.x < st) { r1[threadIdx.x] += r1[threadIdx.x + st]; r2[threadIdx.x] += r2[threadIdx.x + st]; }
        __syncthreads();
    }
    float dv = r1[0], dt = r2[0];
    float2* pv = (float2*)g_projhl + (size_t)i * DD;
    float2* pt = (float2*)g_projhl + (size_t)(BSZ + i) * DD;
    for (int d = threadIdx.x; d < DD; d += 256) {
        pv[d] = split2(dv * tn[d]);
        pt[d] = split2(dt * vn[d]);
    }
}

// ---------------- split v/t embeddings ---------------------------------------
__global__ void __launch_bounds__(256) split_emb_kernel(const float* __restrict__ v,
                                                        const float* __restrict__ t) {
    int e = blockIdx.x * blockDim.x + threadIdx.x;   // 0 .. 1M-1
    if (e < BSZ * DD) {
        ((float2*)g_vhl)[e] = split2(v[e]);
        ((float2*)g_thl)[e] = split2(t[e]);
    }
}

// ---------------- split W / W2 to padded interleaved --------------------------
__global__ void __launch_bounds__(256) split_w_kernel(const float* __restrict__ W,
                                                      float* __restrict__ dsthl, int N) {
    int c = blockIdx.x * blockDim.x + threadIdx.x;
    int row = blockIdx.y;
    if (c < N) {
        ((float2*)dsthl)[(size_t)row * LDCP + c] = split2(W[(size_t)row * N + c]);
    }
}

// ---------------- column inverse norms of W / W2 ------------------------------
__global__ void colinv_kernel(const float* __restrict__ W, int which, int N) {
    int c = blockIdx.x * blockDim.x + threadIdx.x;
    if (c >= N) return;
    float s = 0.f;
    for (int d = 0; d < DD; d++) { float x = W[(size_t)d * N + c]; s += x * x; }
    float inv = 1.f / sqrtf(s);
    if (which) g_invW2[c] = inv; else g_invW[c] = inv;
}

// =====================================================================
// NN GEMM, pre-split tf32 hi/lo operands (3 mma per pair):
//   C[m,n] = scale*invn[n] * sum_k A[m,k]*B[k,n]
// Ahl: [2048][2*1024] interleaved; Bhl: [1024][2*LDCP] interleaved
// grid (m-blocks=16, n-blocks=86); BM=BN=128, BK=16; warp tile 64x32
// =====================================================================
__global__ void __launch_bounds__(256, 2) gemm_nn_tc(const float* __restrict__ Ahl,
                                                     const float* __restrict__ Bhl,
                                                     const float* __restrict__ invn,
                                                     float scale,
                                                     float* __restrict__ Cm,
                                                     int N) {
    __shared__ float As2[128][40];   // cols: 2*k interleaved (32 used), stride 40 -> conflict-free
    __shared__ float Bs2[16][272];   // cols: 2*n interleaved (256 used), stride 272
    const int tid = threadIdx.x;
    const int lane = tid & 31, g = lane >> 2, tig = lane & 3;
    const int warpId = tid >> 5;
    const int warpM = (warpId & 1) * 64;
    const int warpN = (warpId >> 1) * 32;
    const int m0 = blockIdx.x * 128, n0 = blockIdx.y * 128;

    float acc[4][4][4];
#pragma unroll
    for (int i = 0; i < 4; i++)
#pragma unroll
        for (int j = 0; j < 4; j++)
#pragma unroll
            for (int k = 0; k < 4; k++) acc[i][j][k] = 0.f;

    for (int k0 = 0; k0 < 1024; k0 += 16) {
        // A tile: 128 rows x 32 floats
#pragma unroll
        for (int i = 0; i < 4; i++) {
            int f = tid + i * 256;
            int row = f >> 3, c4 = (f & 7) * 4;
            float4 av = *(const float4*)(Ahl + (size_t)(m0 + row) * 2048 + k0 * 2 + c4);
            *(float4*)&As2[row][c4] = av;
        }
        // B tile: 16 rows x 256 floats
#pragma unroll
        for (int i = 0; i < 4; i++) {
            int f = tid + i * 256;
            int row = f >> 6, c4 = (f & 63) * 4;
            float4 bv = *(const float4*)(Bhl + (size_t)(k0 + row) * (2 * LDCP) + n0 * 2 + c4);
            *(float4*)&Bs2[row][c4] = bv;
        }
        __syncthreads();

#pragma unroll
        for (int ks = 0; ks < 2; ks++) {
            uint32_t bh[8], bl[8];
#pragma unroll
            for (int nt = 0; nt < 4; nt++) {
                float2 b0 = *(const float2*)&Bs2[ks * 8 + tig][2 * (warpN + nt * 8 + g)];
                float2 b1 = *(const float2*)&Bs2[ks * 8 + tig + 4][2 * (warpN + nt * 8 + g)];
                bh[2 * nt] = __float_as_uint(b0.x);     bl[2 * nt] = __float_as_uint(b0.y);
                bh[2 * nt + 1] = __float_as_uint(b1.x); bl[2 * nt + 1] = __float_as_uint(b1.y);
            }
#pragma unroll
            for (int mt = 0; mt < 4; mt++) {
                float2 a0 = *(const float2*)&As2[warpM + mt * 16 + g][2 * (ks * 8 + tig)];
                float2 a1 = *(const float2*)&As2[warpM + mt * 16 + g + 8][2 * (ks * 8 + tig)];
                float2 a2 = *(const float2*)&As2[warpM + mt * 16 + g][2 * (ks * 8 + tig + 4)];
                float2 a3 = *(const float2*)&As2[warpM + mt * 16 + g + 8][2 * (ks * 8 + tig + 4)];
                uint32_t ah[4] = {__float_as_uint(a0.x), __float_as_uint(a1.x),
                                  __float_as_uint(a2.x), __float_as_uint(a3.x)};
                uint32_t al[4] = {__float_as_uint(a0.y), __float_as_uint(a1.y),
                                  __float_as_uint(a2.y), __float_as_uint(a3.y)};
#pragma unroll
                for (int nt = 0; nt < 4; nt++) {
                    mma_tf32(acc[mt][nt], ah, bh + 2 * nt);
                    mma_tf32(acc[mt][nt], ah, bl + 2 * nt);
                    mma_tf32(acc[mt][nt], al, bh + 2 * nt);
                }
            }
        }
        __syncthreads();
    }

#pragma unroll
    for (int mt = 0; mt < 4; mt++) {
#pragma unroll
        for (int nt = 0; nt < 4; nt++) {
            int r = m0 + warpM + mt * 16 + g;
            int c = n0 + warpN + nt * 8 + 2 * tig;
            if (c < N) {
                float sc = scale * invn[c];
                Cm[(size_t)r * LDCP + c] = acc[mt][nt][0] * sc;
                Cm[(size_t)(r + 8) * LDCP + c] = acc[mt][nt][2] * sc;
            }
            if (c + 1 < N) {
                float sc = scale * invn[c + 1];
                Cm[(size_t)r * LDCP + c + 1] = acc[mt][nt][1] * sc;
                Cm[(size_t)(r + 8) * LDCP + c + 1] = acc[mt][nt][3] * sc;
            }
        }
    }
}

// =====================================================================
// NT GEMM (1024^3), pre-split hi/lo. B kept row-major [n][2k] in smem
// (same layout as A -> no transpose scatter).
// z: 0 sim = vn@tn^T, 1 vp = v@tn^T, 2 tp = t@vn^T
// =====================================================================
__global__ void __launch_bounds__(256, 2) gemm_nt_tc() {
    __shared__ float As2[128][40];
    __shared__ float Bs2[128][40];
    const float* Ahl; const float* Bthl; float* Cm;
    if (blockIdx.z == 0)      { Ahl = g_normhl;            Bthl = g_normhl + 2 * BSZ * DD; Cm = g_sim; }
    else if (blockIdx.z == 1) { Ahl = g_vhl;               Bthl = g_normhl + 2 * BSZ * DD; Cm = g_vp; }
    else                      { Ahl = g_thl;               Bthl = g_normhl;                Cm = g_tp; }

    const int tid = threadIdx.x;
    const int lane = tid & 31, g = lane >> 2, tig = lane & 3;
    const int warpId = tid >> 5;
    const int warpM = (warpId & 1) * 64;
    const int warpN = (warpId >> 1) * 32;
    const int m0 = blockIdx.x * 128, n0 = blockIdx.y * 128;

    float acc[4][4][4];
#pragma unroll
    for (int i = 0; i < 4; i++)
#pragma unroll
        for (int j = 0; j < 4; j++)
#pragma unroll
            for (int k = 0; k < 4; k++) acc[i][j][k] = 0.f;

    for (int k0 = 0; k0 < 1024; k0 += 16) {
#pragma unroll
        for (int i = 0; i < 4; i++) {
            int f = tid + i * 256;
            int row = f >> 3, c4 = (f & 7) * 4;
            float4 av = *(const float4*)(Ahl + (size_t)(m0 + row) * 2048 + k0 * 2 + c4);
            *(float4*)&As2[row][c4] = av;
            float4 bv = *(const float4*)(Bthl + (size_t)(n0 + row) * 2048 + k0 * 2 + c4);
            *(float4*)&Bs2[row][c4] = bv;
        }
        __syncthreads();

#pragma unroll
        for (int ks = 0; ks < 2; ks++) {
            uint32_t bh[8], bl[8];
#pragma unroll
            for (int nt = 0; nt < 4; nt++) {
                float2 b0 = *(const float2*)&Bs2[warpN + nt * 8 + g][2 * (ks * 8 + tig)];
                float2 b1 = *(const float2*)&Bs2[warpN + nt * 8 + g][2 * (ks * 8 + tig + 4)];
                bh[2 * nt] = __float_as_uint(b0.x);     bl[2 * nt] = __float_as_uint(b0.y);
                bh[2 * nt + 1] = __float_as_uint(b1.x); bl[2 * nt + 1] = __float_as_uint(b1.y);
            }
#pragma unroll
            for (int mt = 0; mt < 4; mt++) {
                float2 a0 = *(const float2*)&As2[warpM + mt * 16 + g][2 * (ks * 8 + tig)];
                float2 a1 = *(const float2*)&As2[warpM + mt * 16 + g + 8][2 * (ks * 8 + tig)];
                float2 a2 = *(const float2*)&As2[warpM + mt * 16 + g][2 * (ks * 8 + tig + 4)];
                float2 a3 = *(const float2*)&As2[warpM + mt * 16 + g + 8][2 * (ks * 8 + tig + 4)];
                uint32_t ah[4] = {__float_as_uint(a0.x), __float_as_uint(a1.x),
                                  __float_as_uint(a2.x), __float_as_uint(a3.x)};
                uint32_t al[4] = {__float_as_uint(a0.y), __float_as_uint(a1.y),
                                  __float_as_uint(a2.y), __float_as_uint(a3.y)};
#pragma unroll
                for (int nt = 0; nt < 4; nt++) {
                    mma_tf32(acc[mt][nt], ah, bh + 2 * nt);
                    mma_tf32(acc[mt][nt], ah, bl + 2 * nt);
                    mma_tf32(acc[mt][nt], al, bh + 2 * nt);
                }
            }
        }
        __syncthreads();
    }

#pragma unroll
    for (int mt = 0; mt < 4; mt++) {
#pragma unroll
        for (int nt = 0; nt < 4; nt++) {
            int r = m0 + warpM + mt * 16 + g;
            int c = n0 + warpN + nt * 8 + 2 * tig;
            Cm[(size_t)r * BSZ + c]           = acc[mt][nt][0];
            Cm[(size_t)r * BSZ + c + 1]       = acc[mt][nt][1];
            Cm[(size_t)(r + 8) * BSZ + c]     = acc[mt][nt][2];
            Cm[(size_t)(r + 8) * BSZ + c + 1] = acc[mt][nt][3];
        }
    }
}

// ---------------- diag extract ------------------------------------------------
__global__ void diag_kernel() {
    int i = blockIdx.x * blockDim.x + threadIdx.x;
    if (i < BSZ) g_diag[i] = g_sim[(size_t)i * BSZ + i];
}

// ---------------- CE row reductions, single pass (fixed shift) ----------------
// logits1: |x| <= 28 exactly; logits2: |x| <= ~35 < 40. exp(x-K) never overflows
// and stays normal (x-K >= -75). Pad columns are 0 -> masked out by j<C.
__global__ void __launch_bounds__(256) reduce_ce_kernel(const int* __restrict__ labels, int C) {
    __shared__ float shf[256];
    __shared__ int   shi[256];
    int r = blockIdx.x;                 // 0..4095
    int tid = threadIdx.x;
    const float* Lr = (r < 2048 ? g_logits1 : g_logits2) + (size_t)(r & 2047) * LDCP;
    const float K = (r < 2048) ? 28.f : 40.f;

    float mx = -1e30f; int mi = 0; float s = 0.f;
    const float4* L4 = (const float4*)Lr;
    for (int j4 = tid; j4 < LDCP / 4; j4 += 256) {
        float4 x = L4[j4];
        int j = 4 * j4;
        if (j < C)     { s += __expf(x.x - K); if (x.x > mx) { mx = x.x; mi = j; } }
        if (j + 1 < C) { s += __expf(x.y - K); if (x.y > mx) { mx = x.y; mi = j + 1; } }
        if (j + 2 < C) { s += __expf(x.z - K); if (x.z > mx) { mx = x.z; mi = j + 2; } }
        if (j + 3 < C) { s += __expf(x.w - K); if (x.w > mx) { mx = x.w; mi = j + 3; } }
    }
    shf[tid] = mx; shi[tid] = mi; __syncthreads();
    for (int st = 128; st > 0; st >>= 1) {
        if (tid < st) {
            float o = shf[tid + st]; int oi = shi[tid + st];
            if (o > shf[tid] || (o == shf[tid] && oi < shi[tid])) { shf[tid] = o; shi[tid] = oi; }
        }
        __syncthreads();
    }
    int MI = shi[0];
    __syncthreads();
    shf[tid] = s; __syncthreads();
    for (int st = 128; st > 0; st >>= 1) {
        if (tid < st) shf[tid] += shf[tid + st];
        __syncthreads();
    }
    if (tid == 0) {
        int lab = labels[r & (BSZ - 1)];
        float loss = logf(shf[0]) + K - Lr[lab];
        if (r < 2048) {
            atomicAdd(&g_acc[0], (double)loss);
        } else {
            atomicAdd(&g_acc[1], (double)loss);
            if (MI == lab) atomicAdd(&g_prec[((r & 2047) < BSZ) ? 0 : 1], 1);
        }
    }
}

// ---------------- pairwise losses (global-align, cmpm, MH) --------------------
__global__ void __launch_bounds__(256) pair_kernel(const int* __restrict__ labels) {
    __shared__ float s_sim[BSZ], s_vp[BSZ], s_tp[BSZ];
    __shared__ float r1[256], r2[256];
    int i = blockIdx.x, tid = threadIdx.x;
    int li = labels[i];
    float dii = g_diag[i];

    for (int j = tid; j < BSZ; j += 256) {
        s_sim[j] = g_sim[(size_t)i * BSZ + j];
        s_vp[j]  = g_vp[(size_t)i * BSZ + j];
        s_tp[j]  = g_tp[(size_t)i * BSZ + j];
    }
    __syncthreads();

    float mv = -1e30f, mt = -1e30f;
    for (int j = tid; j < BSZ; j += 256) { mv = fmaxf(mv, s_vp[j]); mt = fmaxf(mt, s_tp[j]); }
    r1[tid] = mv; r2[tid] = mt; __syncthreads();
    for (int s = 128; s > 0; s >>= 1) {
        if (tid < s) { r1[tid] = fmaxf(r1[tid], r1[tid + s]); r2[tid] = fmaxf(r2[tid], r2[tid + s]); }
        __syncthreads();
    }
    float MV = r1[0], MT = r2[0];
    __syncthreads();

    float sv = 0.f, st = 0.f;
    for (int j = tid; j < BSZ; j += 256) { sv += __expf(s_vp[j] - MV); st += __expf(s_tp[j] - MT); }
    r1[tid] = sv; r2[tid] = st; __syncthreads();
    for (int s = 128; s > 0; s >>= 1) {
        if (tid < s) { r1[tid] += r1[tid + s]; r2[tid] += r2[tid + s]; }
        __syncthreads();
    }
    float LSV = logf(r1[0]), LST = logf(r2[0]);
    __syncthreads();

    float ga = 0.f, cv = 0.f, ct = 0.f, rmax = 0.f;
    for (int j = tid; j < BSZ; j += 256) {
        float sij = s_sim[j];
        int lj = labels[j];
        bool m = (lj == li);
        ga += m ? softplus_ref(-10.f * (sij - 0.6f)) : softplus_ref(40.f * (sij - 0.4f));
        float invrn = rsqrtf((float)g_cnt[lj]);
        float lmn = logf((m ? invrn : 0.f) + 1e-8f);
        float lv = s_vp[j] - MV - LSV;
        cv += __expf(lv) * (lv - lmn);
        float lt = s_tp[j] - MT - LST;
        ct += __expf(lt) * (lt - lmn);
        if (!m) {
            float cs = 0.2f + sij - dii;
            rmax = fmaxf(rmax, cs);
            float ci = 0.2f + sij - g_diag[j];
            if (ci > 0.f) atomicMax(&g_colmax[j], __float_as_int(ci));
        }
    }
    r1[tid] = ga; __syncthreads();
    for (int s = 128; s > 0; s >>= 1) { if (tid < s) r1[tid] += r1[tid + s]; __syncthreads(); }
    if (tid == 0) atomicAdd(&g_acc[2], (double)r1[0]);
    __syncthreads();
    r1[tid] = cv; __syncthreads();
    for (int s = 128; s > 0; s >>= 1) { if (tid < s) r1[tid] += r1[tid + s]; __syncthreads(); }
    if (tid == 0) atomicAdd(&g_acc[3], (double)r1[0]);
    __syncthreads();
    r1[tid] = ct; __syncthreads();
    for (int s = 128; s > 0; s >>= 1) { if (tid < s) r1[tid] += r1[tid + s]; __syncthreads(); }
    if (tid == 0) atomicAdd(&g_acc[4], (double)r1[0]);
    __syncthreads();
    r1[tid] = rmax; __syncthreads();
    for (int s = 128; s > 0; s >>= 1) { if (tid < s) r1[tid] = fmaxf(r1[tid], r1[tid + s]); __syncthreads(); }
    if (tid == 0) atomicAdd(&g_acc[5], (double)r1[0]);
}

// ---------------- finalize ----------------------------------------------------
__global__ void __launch_bounds__(256) finalize_kernel(float* __restrict__ out) {
    __shared__ float red[256];
    int tid = threadIdx.x;
    float s = 0.f;
    for (int j = tid; j < BSZ; j += 256) s += __int_as_float(g_colmax[j]);
    red[tid] = s; __syncthreads();
    for (int st = 128; st > 0; st >>= 1) { if (tid < st) red[tid] += red[tid + st]; __syncthreads(); }
    if (tid == 0) {
        float colsum = red[0];
        out[0] = (float)(g_acc[0] / 1024.0);                    // instance_loss
        out[1] = (float)(2.0 * g_acc[2] / 1024.0);              // global_align_loss
        out[2] = (float)(g_acc[1] / 1024.0);                    // cmpc_loss
        out[3] = (float)((g_acc[3] + g_acc[4]) / 1024.0);       // cmpm_loss
        out[4] = (float)(g_acc[5] + (double)colsum);            // mh_loss
        out[5] = (float)g_prec[0] / 1024.f;                     // visual_prec
        out[6] = (float)g_prec[1] / 1024.f;                     // textual_prec
    }
}

// ---------------- launch ------------------------------------------------------
extern "C" void kernel_launch(void* const* d_in, const int* in_sizes, int n_in,
                              void* d_out, int out_size) {
    const float* v      = (const float*)d_in[0];
    const float* t      = (const float*)d_in[1];
    const float* W      = (const float*)d_in[2];
    const float* W2     = (const float*)d_in[3];
    const int*   labels = (const int*)d_in[4];
    float* out = (float*)d_out;
    int C = in_sizes[2] / DD;   // 11003

    float *p_normhl, *p_projhl, *p_Whl, *p_W2hl, *p_invW, *p_invW2, *p_l1, *p_l2;
    cudaGetSymbolAddress((void**)&p_normhl, g_normhl);
    cudaGetSymbolAddress((void**)&p_projhl, g_projhl);
    cudaGetSymbolAddress((void**)&p_Whl,    g_Whl);
    cudaGetSymbolAddress((void**)&p_W2hl,   g_W2hl);
    cudaGetSymbolAddress((void**)&p_invW,   g_invW);
    cudaGetSymbolAddress((void**)&p_invW2,  g_invW2);
    cudaGetSymbolAddress((void**)&p_l1,     g_logits1);
    cudaGetSymbolAddress((void**)&p_l2,     g_logits2);

    init_kernel<<<4, 256>>>();
    hist_kernel<<<4, 256>>>(labels);
    normalize_kernel<<<2 * BSZ, 256>>>(v, t);
    proj_kernel<<<BSZ, 256>>>(v, t);
    split_emb_kernel<<<(BSZ * DD + 255) / 256, 256>>>(v, t);
    colinv_kernel<<<(C + 255) / 256, 256>>>(W, 0, C);
    colinv_kernel<<<(C + 255) / 256, 256>>>(W2, 1, C);
    dim3 gs((C + 255) / 256, DD);
    split_w_kernel<<<gs, 256>>>(W, p_Whl, C);
    split_w_kernel<<<gs, 256>>>(W2, p_W2hl, C);

    dim3 g1(16, (C + 127) / 128);     // x = m-blocks (fast) -> W tiles shared via L2
    gemm_nn_tc<<<g1, 256>>>(p_normhl, p_Whl,  p_invW,  28.f, p_l1, C);
    gemm_nn_tc<<<g1, 256>>>(p_projhl, p_W2hl, p_invW2, 1.f,  p_l2, C);

    dim3 g2(8, 8, 3);
    gemm_nt_tc<<<g2, 256>>>();

    diag_kernel<<<4, 256>>>();
    reduce_ce_kernel<<<4096, 256>>>(labels, C);
    pair_kernel<<<BSZ, 256>>>(labels);
    finalize_kernel<<<1, 256>>>(out);
}

// round 5
// speedup vs baseline: 1.1143x; 1.1143x over previous
#include <cuda_runtime.h>
#include <math.h>
#include <stdint.h>

#define BSZ 1024
#define DD  1024
#define NTILES 86          // ceil(11003/128)

// ---------------- scratch (device globals; no allocations allowed) ----------
__device__ float g_norm[2 * BSZ * DD];      // rows 0..1023 = vn, 1024..2047 = tn
__device__ float g_proj[2 * BSZ * DD];      // rows 0..1023 = vpt, 1024..2047 = tpv
__device__ float g_invW[11008];
__device__ float g_invW2[11008];
__device__ float g_cesum[NTILES * 4096];    // [tile][row]  partial exp-sums
__device__ unsigned long long g_cemax[NTILES * 4096]; // packed (key, ~col)
__device__ float g_lab[4096];               // label logit per row
__device__ float g_sim[BSZ * BSZ];
__device__ float g_vp[BSZ * BSZ];
__device__ float g_tp[BSZ * BSZ];
__device__ float g_diag[BSZ];
__device__ int   g_cnt[256];
__device__ int   g_colmax[BSZ];             // float bits, values >= 0
__device__ double g_acc[6];                 // 0:ce1 1:ce2 2:ga 3:cmpm_v 4:cmpm_t 5:rowmax_sum
__device__ int   g_prec[2];

// ---------------- helpers ----------------------------------------------------
__device__ __forceinline__ float softplus_ref(float x) {
    return (x > 20.f) ? x : log1pf(__expf(x));
}

__device__ __forceinline__ void split_tf32(float x, uint32_t& hi, uint32_t& lo) {
    uint32_t h;
    asm("cvt.rna.tf32.f32 %0, %1;" : "=r"(h) : "f"(x));
    float l = x - __uint_as_float(h);
    uint32_t lw;
    asm("cvt.rna.tf32.f32 %0, %1;" : "=r"(lw) : "f"(l));
    hi = h; lo = lw;
}

__device__ __forceinline__ void mma_tf32(float* c, const uint32_t* a, const uint32_t* b) {
    asm volatile(
        "mma.sync.aligned.m16n8k8.row.col.f32.tf32.tf32.f32 "
        "{%0,%1,%2,%3}, {%4,%5,%6,%7}, {%8,%9}, {%0,%1,%2,%3};"
        : "+f"(c[0]), "+f"(c[1]), "+f"(c[2]), "+f"(c[3])
        : "r"(a[0]), "r"(a[1]), "r"(a[2]), "r"(a[3]), "r"(b[0]), "r"(b[1]));
}

// order-preserving float -> uint key
__device__ __forceinline__ uint32_t fkey(float f) {
    uint32_t u = __float_as_uint(f);
    return ((int)u < 0) ? ~u : (u | 0x80000000u);
}

// ---------------- init / histogram ------------------------------------------
__global__ void init_kernel() {
    int t = blockIdx.x * blockDim.x + threadIdx.x;
    if (t < 6)    g_acc[t] = 0.0;
    if (t < 2)    g_prec[t] = 0;
    if (t < 256)  g_cnt[t] = 0;
    if (t < BSZ)  g_colmax[t] = 0;
}

__global__ void hist_kernel(const int* __restrict__ labels) {
    int t = blockIdx.x * blockDim.x + threadIdx.x;
    if (t < BSZ) atomicAdd(&g_cnt[labels[t]], 1);
}

// ---------------- row normalize (vn, tn) -------------------------------------
__global__ void __launch_bounds__(256) normalize_kernel(const float* __restrict__ v,
                                                        const float* __restrict__ t) {
    __shared__ float red[256];
    int r = blockIdx.x;                     // 0..2047
    const float* src = (r < BSZ ? v : t) + (size_t)(r & (BSZ - 1)) * DD;
    float s = 0.f;
    for (int d = threadIdx.x; d < DD; d += 256) { float x = src[d]; s += x * x; }
    red[threadIdx.x] = s; __syncthreads();
    for (int st = 128; st > 0; st >>= 1) {
        if (threadIdx.x < st) red[threadIdx.x] += red[threadIdx.x + st];
        __syncthreads();
    }
    float inv = 1.f / sqrtf(red[0]);
    float* dst = g_norm + (size_t)r * DD;
    for (int d = threadIdx.x; d < DD; d += 256) dst[d] = src[d] * inv;
}

// ---------------- projections vpt, tpv ---------------------------------------
__global__ void __launch_bounds__(256) proj_kernel(const float* __restrict__ v,
                                                   const float* __restrict__ t) {
    __shared__ float r1[256], r2[256];
    int i = blockIdx.x;
    const float* vn = g_norm + (size_t)i * DD;
    const float* tn = g_norm + (size_t)(BSZ + i) * DD;
    const float* vi = v + (size_t)i * DD;
    const float* ti = t + (size_t)i * DD;
    float a = 0.f, b = 0.f;
    for (int d = threadIdx.x; d < DD; d += 256) { a += vi[d] * tn[d]; b += ti[d] * vn[d]; }
    r1[threadIdx.x] = a; r2[threadIdx.x] = b; __syncthreads();
    for (int st = 128; st > 0; st >>= 1) {
        if (threadIdx.x < st) { r1[threadIdx.x] += r1[threadIdx.x + st]; r2[threadIdx.x] += r2[threadIdx.x + st]; }
        __syncthreads();
    }
    float dv = r1[0], dt = r2[0];
    float* pv = g_proj + (size_t)i * DD;
    float* pt = g_proj + (size_t)(BSZ + i) * DD;
    for (int d = threadIdx.x; d < DD; d += 256) { pv[d] = dv * tn[d]; pt[d] = dt * vn[d]; }
}

// ---------------- column inverse norms of W / W2 ------------------------------
__global__ void colinv_kernel(const float* __restrict__ W, int which, int N) {
    int c = blockIdx.x * blockDim.x + threadIdx.x;
    if (c >= N) return;
    float s = 0.f;
    for (int d = 0; d < DD; d++) { float x = W[(size_t)d * N + c]; s += x * x; }
    float inv = 1.f / sqrtf(s);
    if (which) g_invW2[c] = inv; else g_invW[c] = inv;
}

// =====================================================================
// NN GEMM (3xTF32, in-loop split) with FUSED CE epilogue.
// logits are never stored: epilogue emits per-row-tile partial exp-sums
// (fixed shift kshift), packed max (value, ~col), and the label logit.
//   val[m,n] = scale*invn[n] * sum_k A[m,k]*Bm[k,n]
// grid: x = n-tiles (86), y = m-tiles (16)
// =====================================================================
__global__ void __launch_bounds__(256, 2) gemm_nn_ce(const float* __restrict__ A,
                                                     const float* __restrict__ Bm,
                                                     const float* __restrict__ invn,
                                                     const int* __restrict__ labels,
                                                     float scale, float kshift,
                                                     int row_base, int N) {
    __shared__ float As[128][20];
    __shared__ float Bs[16][136];
    __shared__ float rowsum[128];
    __shared__ unsigned long long rowmax[128];
    const int tid = threadIdx.x;
    const int lane = tid & 31, g = lane >> 2, tig = lane & 3;
    const int warpId = tid >> 5;
    const int warpM = (warpId & 1) * 64;
    const int warpN = (warpId >> 1) * 32;
    const int m0 = blockIdx.y * 128, n0 = blockIdx.x * 128;

    const int ar = tid >> 2;            // 0..63
    const int ac = (tid & 3) * 4;

    float acc[4][4][4];
#pragma unroll
    for (int i = 0; i < 4; i++)
#pragma unroll
        for (int j = 0; j < 4; j++)
#pragma unroll
            for (int k = 0; k < 4; k++) acc[i][j][k] = 0.f;

    for (int k0 = 0; k0 < 1024; k0 += 16) {
        float4 a0 = *(const float4*)(A + (size_t)(m0 + ar) * 1024 + k0 + ac);
        float4 a1 = *(const float4*)(A + (size_t)(m0 + ar + 64) * 1024 + k0 + ac);
        As[ar][ac + 0] = a0.x; As[ar][ac + 1] = a0.y; As[ar][ac + 2] = a0.z; As[ar][ac + 3] = a0.w;
        As[ar + 64][ac + 0] = a1.x; As[ar + 64][ac + 1] = a1.y; As[ar + 64][ac + 2] = a1.z; As[ar + 64][ac + 3] = a1.w;
#pragma unroll
        for (int i = 0; i < 8; i++) {
            int e = tid + i * 256;
            int k = e >> 7, n = e & 127;
            int col = n0 + n;
            Bs[k][n] = (col < N) ? __ldg(Bm + (size_t)(k0 + k) * N + col) : 0.f;
        }
        __syncthreads();

#pragma unroll
        for (int ks = 0; ks < 2; ks++) {
            uint32_t bhi[8], blo[8];
#pragma unroll
            for (int nt = 0; nt < 4; nt++) {
                float b0 = Bs[ks * 8 + tig][warpN + nt * 8 + g];
                float b1 = Bs[ks * 8 + tig + 4][warpN + nt * 8 + g];
                split_tf32(b0, bhi[2 * nt], blo[2 * nt]);
                split_tf32(b1, bhi[2 * nt + 1], blo[2 * nt + 1]);
            }
#pragma unroll
            for (int mt = 0; mt < 4; mt++) {
                uint32_t ahi[4], alo[4];
                float a_0 = As[warpM + mt * 16 + g][ks * 8 + tig];
                float a_1 = As[warpM + mt * 16 + g + 8][ks * 8 + tig];
                float a_2 = As[warpM + mt * 16 + g][ks * 8 + tig + 4];
                float a_3 = As[warpM + mt * 16 + g + 8][ks * 8 + tig + 4];
                split_tf32(a_0, ahi[0], alo[0]);
                split_tf32(a_1, ahi[1], alo[1]);
                split_tf32(a_2, ahi[2], alo[2]);
                split_tf32(a_3, ahi[3], alo[3]);
#pragma unroll
                for (int nt = 0; nt < 4; nt++) {
                    mma_tf32(acc[mt][nt], ahi, bhi + 2 * nt);
                    mma_tf32(acc[mt][nt], ahi, blo + 2 * nt);
                    mma_tf32(acc[mt][nt], alo, bhi + 2 * nt);
                }
            }
        }
        __syncthreads();
    }

    // ---------- fused CE epilogue ----------
    if (tid < 128) { rowsum[tid] = 0.f; rowmax[tid] = 0ull; }
    __syncthreads();

#pragma unroll
    for (int mt = 0; mt < 4; mt++) {
#pragma unroll
        for (int rh = 0; rh < 2; rh++) {
            int row_local = warpM + mt * 16 + g + rh * 8;
            int lab = labels[(m0 + row_local) & (BSZ - 1)];
            float lsum = 0.f;
            unsigned long long lmax = 0ull;
            float labval = 0.f;
            bool haslab = false;
#pragma unroll
            for (int nt = 0; nt < 4; nt++) {
#pragma unroll
                for (int h = 0; h < 2; h++) {
                    int c = n0 + warpN + nt * 8 + 2 * tig + h;
                    if (c < N) {
                        float val = acc[mt][nt][rh * 2 + h] * scale * invn[c];
                        lsum += __expf(val - kshift);
                        unsigned long long p = ((unsigned long long)fkey(val) << 32)
                                             | (unsigned)(0xFFFFFFFFu - c);
                        lmax = (p > lmax) ? p : lmax;
                        if (c == lab) { haslab = true; labval = val; }
                    }
                }
            }
            atomicAdd(&rowsum[row_local], lsum);
            atomicMax(&rowmax[row_local], lmax);
            if (haslab) g_lab[row_base + m0 + row_local] = labval;
        }
    }
    __syncthreads();

    if (tid < 128) {
        int gr = row_base + m0 + tid;
        g_cesum[(size_t)blockIdx.x * 4096 + gr] = rowsum[tid];
        g_cemax[(size_t)blockIdx.x * 4096 + gr] = rowmax[tid];
    }
}

// ---------------- CE finish: reduce tile partials per row ---------------------
__global__ void __launch_bounds__(128) ce_finish_kernel(const int* __restrict__ labels) {
    __shared__ double red[128];
    int r = blockIdx.x * 128 + threadIdx.x;   // 0..4095
    double s = 0.0;
    unsigned long long m = 0ull;
#pragma unroll 2
    for (int tile = 0; tile < NTILES; tile++) {
        s += (double)g_cesum[(size_t)tile * 4096 + r];
        unsigned long long p = g_cemax[(size_t)tile * 4096 + r];
        m = (p > m) ? p : m;
    }
    float K = (r < 2048) ? 28.f : 40.f;
    double loss = log(s) + (double)K - (double)g_lab[r];

    if (r >= 2048) {
        int idx = (int)(0xFFFFFFFFu - (unsigned)(m & 0xFFFFFFFFull));
        int lab = labels[r & (BSZ - 1)];
        if (idx == lab) atomicAdd(&g_prec[((r - 2048) < BSZ) ? 0 : 1], 1);
    }

    red[threadIdx.x] = loss; __syncthreads();
    for (int st = 64; st > 0; st >>= 1) {
        if (threadIdx.x < st) red[threadIdx.x] += red[threadIdx.x + st];
        __syncthreads();
    }
    if (threadIdx.x == 0) atomicAdd(&g_acc[(r < 2048) ? 0 : 1], red[0]);
}

// =====================================================================
// NT GEMM (1024^3), 3xTF32 (unchanged from R3 measured version)
// z: 0 sim = vn@tn^T, 1 vp = v@tn^T, 2 tp = t@vn^T
// =====================================================================
__global__ void __launch_bounds__(256, 2) gemm_nt_tc(const float* __restrict__ v,
                                                     const float* __restrict__ t) {
    __shared__ float As[128][20];
    __shared__ float Bs[16][136];
    const float* A; const float* Bt; float* Cm;
    if (blockIdx.z == 0)      { A = g_norm; Bt = g_norm + BSZ * DD; Cm = g_sim; }
    else if (blockIdx.z == 1) { A = v;      Bt = g_norm + BSZ * DD; Cm = g_vp; }
    else                      { A = t;      Bt = g_norm;            Cm = g_tp; }

    const int tid = threadIdx.x;
    const int lane = tid & 31, g = lane >> 2, tig = lane & 3;
    const int warpId = tid >> 5;
    const int warpM = (warpId & 1) * 64;
    const int warpN = (warpId >> 1) * 32;
    const int m0 = blockIdx.y * 128, n0 = blockIdx.x * 128;

    const int ar = tid >> 2;
    const int ac = (tid & 3) * 4;

    float acc[4][4][4];
#pragma unroll
    for (int i = 0; i < 4; i++)
#pragma unroll
        for (int j = 0; j < 4; j++)
#pragma unroll
            for (int k = 0; k < 4; k++) acc[i][j][k] = 0.f;

    for (int k0 = 0; k0 < 1024; k0 += 16) {
        float4 a0 = *(const float4*)(A + (size_t)(m0 + ar) * 1024 + k0 + ac);
        float4 a1 = *(const float4*)(A + (size_t)(m0 + ar + 64) * 1024 + k0 + ac);
        As[ar][ac + 0] = a0.x; As[ar][ac + 1] = a0.y; As[ar][ac + 2] = a0.z; As[ar][ac + 3] = a0.w;
        As[ar + 64][ac + 0] = a1.x; As[ar + 64][ac + 1] = a1.y; As[ar + 64][ac + 2] = a1.z; As[ar + 64][ac + 3] = a1.w;
#pragma unroll
        for (int i = 0; i < 2; i++) {
            int e4 = tid + i * 256;     // 0..511
            int n = e4 >> 2;            // 0..127
            int kq = (e4 & 3) * 4;      // 0,4,8,12
            float4 bv = *(const float4*)(Bt + (size_t)(n0 + n) * 1024 + k0 + kq);
            Bs[kq + 0][n] = bv.x; Bs[kq + 1][n] = bv.y; Bs[kq + 2][n] = bv.z; Bs[kq + 3][n] = bv.w;
        }
        __syncthreads();

#pragma unroll
        for (int ks = 0; ks < 2; ks++) {
            uint32_t bhi[8], blo[8];
#pragma unroll
            for (int nt = 0; nt < 4; nt++) {
                float b0 = Bs[ks * 8 + tig][warpN + nt * 8 + g];
                float b1 = Bs[ks * 8 + tig + 4][warpN + nt * 8 + g];
                split_tf32(b0, bhi[2 * nt], blo[2 * nt]);
                split_tf32(b1, bhi[2 * nt + 1], blo[2 * nt + 1]);
            }
#pragma unroll
            for (int mt = 0; mt < 4; mt++) {
                uint32_t ahi[4], alo[4];
                float a_0 = As[warpM + mt * 16 + g][ks * 8 + tig];
                float a_1 = As[warpM + mt * 16 + g + 8][ks * 8 + tig];
                float a_2 = As[warpM + mt * 16 + g][ks * 8 + tig + 4];
                float a_3 = As[warpM + mt * 16 + g + 8][ks * 8 + tig + 4];
                split_tf32(a_0, ahi[0], alo[0]);
                split_tf32(a_1, ahi[1], alo[1]);
                split_tf32(a_2, ahi[2], alo[2]);
                split_tf32(a_3, ahi[3], alo[3]);
#pragma unroll
                for (int nt = 0; nt < 4; nt++) {
                    mma_tf32(acc[mt][nt], ahi, bhi + 2 * nt);
                    mma_tf32(acc[mt][nt], ahi, blo + 2 * nt);
                    mma_tf32(acc[mt][nt], alo, bhi + 2 * nt);
                }
            }
        }
        __syncthreads();
    }

#pragma unroll
    for (int mt = 0; mt < 4; mt++) {
#pragma unroll
        for (int nt = 0; nt < 4; nt++) {
            int r = m0 + warpM + mt * 16 + g;
            int c = n0 + warpN + nt * 8 + 2 * tig;
            Cm[(size_t)r * BSZ + c]           = acc[mt][nt][0];
            Cm[(size_t)r * BSZ + c + 1]       = acc[mt][nt][1];
            Cm[(size_t)(r + 8) * BSZ + c]     = acc[mt][nt][2];
            Cm[(size_t)(r + 8) * BSZ + c + 1] = acc[mt][nt][3];
        }
    }
}

// ---------------- diag extract ------------------------------------------------
__global__ void diag_kernel() {
    int i = blockIdx.x * blockDim.x + threadIdx.x;
    if (i < BSZ) g_diag[i] = g_sim[(size_t)i * BSZ + i];
}

// ---------------- pairwise losses (global-align, cmpm, MH) --------------------
__global__ void __launch_bounds__(256) pair_kernel(const int* __restrict__ labels) {
    __shared__ float s_sim[BSZ], s_vp[BSZ], s_tp[BSZ];
    __shared__ float r1[256], r2[256];
    int i = blockIdx.x, tid = threadIdx.x;
    int li = labels[i];
    float dii = g_diag[i];

    for (int j = tid; j < BSZ; j += 256) {
        s_sim[j] = g_sim[(size_t)i * BSZ + j];
        s_vp[j]  = g_vp[(size_t)i * BSZ + j];
        s_tp[j]  = g_tp[(size_t)i * BSZ + j];
    }
    __syncthreads();

    float mv = -1e30f, mt = -1e30f;
    for (int j = tid; j < BSZ; j += 256) { mv = fmaxf(mv, s_vp[j]); mt = fmaxf(mt, s_tp[j]); }
    r1[tid] = mv; r2[tid] = mt; __syncthreads();
    for (int s = 128; s > 0; s >>= 1) {
        if (tid < s) { r1[tid] = fmaxf(r1[tid], r1[tid + s]); r2[tid] = fmaxf(r2[tid], r2[tid + s]); }
        __syncthreads();
    }
    float MV = r1[0], MT = r2[0];
    __syncthreads();

    float sv = 0.f, st = 0.f;
    for (int j = tid; j < BSZ; j += 256) { sv += __expf(s_vp[j] - MV); st += __expf(s_tp[j] - MT); }
    r1[tid] = sv; r2[tid] = st; __syncthreads();
    for (int s = 128; s > 0; s >>= 1) {
        if (tid < s) { r1[tid] += r1[tid + s]; r2[tid] += r2[tid + s]; }
        __syncthreads();
    }
    float LSV = logf(r1[0]), LST = logf(r2[0]);
    __syncthreads();

    float ga = 0.f, cv = 0.f, ct = 0.f, rmax = 0.f;
    for (int j = tid; j < BSZ; j += 256) {
        float sij = s_sim[j];
        int lj = labels[j];
        bool m = (lj == li);
        ga += m ? softplus_ref(-10.f * (sij - 0.6f)) : softplus_ref(40.f * (sij - 0.4f));
        float invrn = rsqrtf((float)g_cnt[lj]);
        float lmn = logf((m ? invrn : 0.f) + 1e-8f);
        float lv = s_vp[j] - MV - LSV;
        cv += __expf(lv) * (lv - lmn);
        float lt = s_tp[j] - MT - LST;
        ct += __expf(lt) * (lt - lmn);
        if (!m) {
            float cs = 0.2f + sij - dii;
            rmax = fmaxf(rmax, cs);
            float ci = 0.2f + sij - g_diag[j];
            if (ci > 0.f) atomicMax(&g_colmax[j], __float_as_int(ci));
        }
    }
    r1[tid] = ga; __syncthreads();
    for (int s = 128; s > 0; s >>= 1) { if (tid < s) r1[tid] += r1[tid + s]; __syncthreads(); }
    if (tid == 0) atomicAdd(&g_acc[2], (double)r1[0]);
    __syncthreads();
    r1[tid] = cv; __syncthreads();
    for (int s = 128; s > 0; s >>= 1) { if (tid < s) r1[tid] += r1[tid + s]; __syncthreads(); }
    if (tid == 0) atomicAdd(&g_acc[3], (double)r1[0]);
    __syncthreads();
    r1[tid] = ct; __syncthreads();
    for (int s = 128; s > 0; s >>= 1) { if (tid < s) r1[tid] += r1[tid + s]; __syncthreads(); }
    if (tid == 0) atomicAdd(&g_acc[4], (double)r1[0]);
    __syncthreads();
    r1[tid] = rmax; __syncthreads();
    for (int s = 128; s > 0; s >>= 1) { if (tid < s) r1[tid] = fmaxf(r1[tid], r1[tid + s]); __syncthreads(); }
    if (tid == 0) atomicAdd(&g_acc[5], (double)r1[0]);
}

// ---------------- finalize ----------------------------------------------------
__global__ void __launch_bounds__(256) finalize_kernel(float* __restrict__ out) {
    __shared__ float red[256];
    int tid = threadIdx.x;
    float s = 0.f;
    for (int j = tid; j < BSZ; j += 256) s += __int_as_float(g_colmax[j]);
    red[tid] = s; __syncthreads();
    for (int st = 128; st > 0; st >>= 1) { if (tid < st) red[tid] += red[tid + st]; __syncthreads(); }
    if (tid == 0) {
        float colsum = red[0];
        out[0] = (float)(g_acc[0] / 1024.0);                    // instance_loss
        out[1] = (float)(2.0 * g_acc[2] / 1024.0);              // global_align_loss
        out[2] = (float)(g_acc[1] / 1024.0);                    // cmpc_loss
        out[3] = (float)((g_acc[3] + g_acc[4]) / 1024.0);       // cmpm_loss
        out[4] = (float)(g_acc[5] + (double)colsum);            // mh_loss
        out[5] = (float)g_prec[0] / 1024.f;                     // visual_prec
        out[6] = (float)g_prec[1] / 1024.f;                     // textual_prec
    }
}

// ---------------- launch ------------------------------------------------------
extern "C" void kernel_launch(void* const* d_in, const int* in_sizes, int n_in,
                              void* d_out, int out_size) {
    const float* v      = (const float*)d_in[0];
    const float* t      = (const float*)d_in[1];
    const float* W      = (const float*)d_in[2];
    const float* W2     = (const float*)d_in[3];
    const int*   labels = (const int*)d_in[4];
    float* out = (float*)d_out;
    int C = in_sizes[2] / DD;   // 11003

    float *p_norm, *p_proj, *p_invW, *p_invW2;
    cudaGetSymbolAddress((void**)&p_norm,  g_norm);
    cudaGetSymbolAddress((void**)&p_proj,  g_proj);
    cudaGetSymbolAddress((void**)&p_invW,  g_invW);
    cudaGetSymbolAddress((void**)&p_invW2, g_invW2);

    init_kernel<<<4, 256>>>();
    hist_kernel<<<4, 256>>>(labels);
    normalize_kernel<<<2 * BSZ, 256>>>(v, t);
    proj_kernel<<<BSZ, 256>>>(v, t);
    colinv_kernel<<<(C + 255) / 256, 256>>>(W, 0, C);
    colinv_kernel<<<(C + 255) / 256, 256>>>(W2, 1, C);

    dim3 g1((C + 127) / 128, 2 * BSZ / 128);
    gemm_nn_ce<<<g1, 256>>>(p_norm, W,  p_invW,  labels, 28.f, 28.f, 0,    C);
    gemm_nn_ce<<<g1, 256>>>(p_proj, W2, p_invW2, labels, 1.f,  40.f, 2048, C);

    dim3 g2(BSZ / 128, BSZ / 128, 3);
    gemm_nt_tc<<<g2, 256>>>(v, t);

    ce_finish_kernel<<<32, 128>>>(labels);
    diag_kernel<<<4, 256>>>();
    pair_kernel<<<BSZ, 256>>>(labels);
    finalize_kernel<<<1, 256>>>(out);
}